// round 6
// baseline (speedup 1.0000x reference)
#include <cuda_runtime.h>
#include <cuda_bf16.h>
#include <cstdint>

// Batched complex QR (Q only), LAPACK Householder convention.
//   Input : x [B, 64, 16, 2] float32   Output: q [B, 64, 16, 2] float32
//
// Two matrices per warp (16-lane groups, lane owns rows l, l+16, l+32, l+48).
// Single fused butterfly per elimination step; packed fma.rn.f32x2 everywhere.
// This round: 3 blocks/SM — rotated (pad-free) SMEM X staging + reg target 170.

typedef unsigned long long u64;
#define NR   16
#define WPB  4
#define MPB  (WPB * 2)
#define SX_F2 (MPB * 64 * 16)          // 8192 float2 = 64 KB
#define SR_F2 (MPB * 136)              // 1088 float2 = 8.5 KB
#define SMEM_BYTES ((SX_F2 + SR_F2) * (int)sizeof(float2))   // 74240
#define FULLM 0xffffffffu

__device__ __forceinline__ u64 PK(float lo, float hi) {
    u64 r; asm("mov.b64 %0,{%1,%2};" : "=l"(r) : "f"(lo), "f"(hi)); return r;
}
__device__ __forceinline__ void UPK(u64 v, float& lo, float& hi) {
    asm("mov.b64 {%0,%1},%2;" : "=f"(lo), "=f"(hi) : "l"(v));
}
__device__ __forceinline__ u64 DUP(float x) { return PK(x, x); }
__device__ __forceinline__ u64 FMA2(u64 a, u64 b, u64 c) {
    u64 d; asm("fma.rn.f32x2 %0,%1,%2,%3;" : "=l"(d) : "l"(a), "l"(b), "l"(c)); return d;
}
__device__ __forceinline__ u64 MUL2(u64 a, u64 b) {
    u64 d; asm("mul.rn.f32x2 %0,%1,%2;" : "=l"(d) : "l"(a), "l"(b)); return d;
}
__device__ __forceinline__ u64 ADD2(u64 a, u64 b) {
    u64 d; asm("add.rn.f32x2 %0,%1,%2;" : "=l"(d) : "l"(a), "l"(b)); return d;
}
__device__ __forceinline__ u64 SHX2(u64 v, int s) {
    float a, b; UPK(v, a, b);
    a = __shfl_xor_sync(FULLM, a, s);
    b = __shfl_xor_sync(FULLM, b, s);
    return PK(a, b);
}
__device__ __forceinline__ u64 SHI2(u64 v, int src) {
    float a, b; UPK(v, a, b);
    a = __shfl_sync(FULLM, a, src);
    b = __shfl_sync(FULLM, b, src);
    return PK(a, b);
}
// rotated (pad-free, conflict-free) sx addressing, in float2 units
__device__ __forceinline__ int SXI(int row, int col) {
    return row * 16 + ((col + row) & 15);
}

__global__ void __launch_bounds__(128, 3)
qr_householder_kernel(const float* __restrict__ in,
                      float* __restrict__ out,
                      int B)
{
    extern __shared__ float2 smem[];
    float2* sx = smem;             // [MPB][64][16], rotated rows
    float2* sR = smem + SX_F2;     // packed upper triangles, 136 per matrix

    const int tid  = threadIdx.x;
    const int warp = tid >> 5;
    const int lane = tid & 31;
    const int g    = lane >> 4;
    const int l    = lane & 15;
    const int mw   = warp * 2;
    const long long b0 = (long long)blockIdx.x * MPB;
    if (b0 + mw >= B) return;

    // ---- coalesced load of this warp's 2 matrices -> rotated SMEM ----
    {
        const float4* src = (const float4*)(in + (b0 + mw) * 2048);
#pragma unroll
        for (int i = 0; i < 32; i++) {
            const int idx = i * 32 + lane;
            const float4 v = src[idx];
            const int m   = idx >> 9;
            const int rem = idx & 511;
            const int row = rem >> 3;
            const int cp  = rem & 7;
            float2* base = sx + (mw + m) * 1024;
            base[SXI(row, 2 * cp)]     = make_float2(v.x, v.y);
            base[SXI(row, 2 * cp + 1)] = make_float2(v.z, v.w);
        }
    }
    __syncwarp();

    float2* sxm = sx + (mw + g) * 1024;
    float2* sRm = sR + (mw + g) * 136;

    // ---- working copy, packed planes: column pair p = cols (2p, 2p+1) ----
    u64 are[4][8], aim[4][8];
#pragma unroll
    for (int r = 0; r < 4; r++)
#pragma unroll
        for (int p = 0; p < 8; p++) {
            const float2 c0 = sxm[SXI(l + 16 * r, 2 * p)];
            const float2 c1 = sxm[SXI(l + 16 * r, 2 * p + 1)];
            are[r][p] = PK(c0.x, c1.x);
            aim[r][p] = PK(c0.y, c1.y);
        }

    // ================= Householder elimination (cgeqrf) =================
#pragma unroll
    for (int j = 0; j < NR; j++) {
        const int jp   = j >> 1;
        const int srcj = (g << 4) | j;

        float xr[4], xi[4];
#pragma unroll
        for (int r = 0; r < 4; r++) {
            float lo, hi; UPK(are[r][jp], lo, hi);
            xr[r] = (j & 1) ? hi : lo;
            UPK(aim[r][jp], lo, hi);
            xi[r] = (j & 1) ? hi : lo;
        }
        const float alr = __shfl_sync(FULLM, xr[0], srcj);   // alpha
        const float ali = __shfl_sync(FULLM, xi[0], srcj);
        const float x0r = (l > j) ? xr[0] : 0.f;
        const float x0i = (l > j) ? xi[0] : 0.f;

        float t = xr[1]*xr[1] + xi[1]*xi[1] + xr[2]*xr[2] + xi[2]*xi[2]
                + xr[3]*xr[3] + xi[3]*xi[3] + x0r*x0r + x0i*x0i;

        // u_k = sum_tail conj(x) * a_k   (packed partials)
        u64 ur[8], ui[8];
        {
            const u64 X1 = DUP(xr[1]), Y1 = DUP(xi[1]), nY1 = DUP(-xi[1]);
            const u64 X2 = DUP(xr[2]), Y2 = DUP(xi[2]), nY2 = DUP(-xi[2]);
            const u64 X3 = DUP(xr[3]), Y3 = DUP(xi[3]), nY3 = DUP(-xi[3]);
            const u64 X0 = DUP(x0r),   Y0 = DUP(x0i),   nY0 = DUP(-x0i);
#pragma unroll
            for (int p = 0; p < 8; p++) {
                if (2 * p + 1 <= j) continue;
                u64 r_ = FMA2(X1, are[1][p], MUL2(Y1,  aim[1][p]));
                u64 i_ = FMA2(X1, aim[1][p], MUL2(nY1, are[1][p]));
                r_ = FMA2(X2, are[2][p], FMA2(Y2,  aim[2][p], r_));
                i_ = FMA2(X2, aim[2][p], FMA2(nY2, are[2][p], i_));
                r_ = FMA2(X3, are[3][p], FMA2(Y3,  aim[3][p], r_));
                i_ = FMA2(X3, aim[3][p], FMA2(nY3, are[3][p], i_));
                r_ = FMA2(X0, are[0][p], FMA2(Y0,  aim[0][p], r_));
                i_ = FMA2(X0, aim[0][p], FMA2(nY0, are[0][p], i_));
                ur[p] = r_; ui[p] = i_;
            }
        }

        // single fused butterfly: t + all u_k
#pragma unroll
        for (int s = 8; s; s >>= 1) {
            t += __shfl_xor_sync(FULLM, t, s);
#pragma unroll
            for (int p = 0; p < 8; p++) {
                if (2 * p + 1 <= j) continue;
                ur[p] = ADD2(ur[p], SHX2(ur[p], s));
                ui[p] = ADD2(ui[p], SHX2(ui[p], s));
            }
        }

        // Householder scalars (LAPACK clarfg convention), rsqrt-based
        float bet, idr, idi, ctr, cti;
        if (t == 0.f && ali == 0.f) {
            bet = alr; idr = 0.f; idi = 0.f; ctr = 0.f; cti = 0.f;  // tau = 0
        } else {
            const float ss = alr * alr + ali * ali + t;
            const float rn = rsqrtf(ss);
            const float nrm = ss * rn;
            const float sgn = (alr >= 0.f) ? 1.f : -1.f;
            bet = -sgn * nrm;
            const float ib = -sgn * rn;               // 1/bet
            const float dr = alr - bet, di = ali;
            const float dd = __fdividef(1.f, dr * dr + di * di);
            idr = dr * dd; idi = -di * dd;            // 1/(alpha-beta)
            ctr = (bet - alr) * ib; cti = ali * ib;   // conj(tau)
        }

        // reflector v over this lane's rows
        float vr0, vi0;
        if (l > j)       { vr0 = idr*xr[0] - idi*xi[0]; vi0 = idr*xi[0] + idi*xr[0]; }
        else if (l == j) { vr0 = 1.f; vi0 = 0.f; }
        else             { vr0 = 0.f; vi0 = 0.f; }
        const float vr1 = idr*xr[1] - idi*xi[1], vi1 = idr*xi[1] + idi*xr[1];
        const float vr2 = idr*xr[2] - idi*xi[2], vi2 = idr*xi[2] + idi*xr[2];
        const float vr3 = idr*xr[3] - idi*xi[3], vi3 = idr*xi[3] + idi*xr[3];
        const u64 V0r = DUP(vr0), V0i = DUP(vi0), V1r = DUP(vr1), V1i = DUP(vi1);
        const u64 V2r = DUP(vr2), V2i = DUP(vi2), V3r = DUP(vr3), V3i = DUP(vi3);
        const u64 IDR = DUP(idr), IDI = DUP(idi), nIDI = DUP(-idi);
        const u64 CTR = DUP(ctr), nCTR = DUP(-ctr), CTI = DUP(cti), nCTI = DUP(-cti);

        // per pair: row-j broadcast, w = ajk + conj(inv)*u, g = ctau*w, a -= g*v
        // (loop order starts at the next step's critical pair naturally)
#pragma unroll
        for (int p = 0; p < 8; p++) {
            if (2 * p + 1 <= j) continue;
            const u64 ajr = SHI2(are[0][p], srcj);
            const u64 aji = SHI2(aim[0][p], srcj);
            const u64 wr = FMA2(IDR, ur[p], FMA2(IDI,  ui[p], ajr));
            const u64 wi = FMA2(IDR, ui[p], FMA2(nIDI, ur[p], aji));
            const u64 ngr = FMA2(nCTR, wr, MUL2(CTI,  wi));   // -Re(g)
            const u64 gi  = FMA2(CTR,  wi, MUL2(CTI,  wr));   //  Im(g)
            const u64 ngi = FMA2(nCTR, wi, MUL2(nCTI, wr));   // -Im(g)
            are[0][p] = FMA2(ngr, V0r, FMA2(gi,  V0i, are[0][p]));
            aim[0][p] = FMA2(ngr, V0i, FMA2(ngi, V0r, aim[0][p]));
            are[1][p] = FMA2(ngr, V1r, FMA2(gi,  V1i, are[1][p]));
            aim[1][p] = FMA2(ngr, V1i, FMA2(ngi, V1r, aim[1][p]));
            are[2][p] = FMA2(ngr, V2r, FMA2(gi,  V2i, are[2][p]));
            aim[2][p] = FMA2(ngr, V2i, FMA2(ngi, V2r, aim[2][p]));
            are[3][p] = FMA2(ngr, V3r, FMA2(gi,  V3i, are[3][p]));
            aim[3][p] = FMA2(ngr, V3i, FMA2(ngi, V3r, aim[3][p]));
        }

        // R diagonal (beta, real) on lane j
        if (l == j) {
            float lo, hi;
            UPK(are[0][jp], lo, hi);
            are[0][jp] = (j & 1) ? PK(lo, bet) : PK(bet, hi);
            UPK(aim[0][jp], lo, hi);
            aim[0][jp] = (j & 1) ? PK(lo, 0.f) : PK(0.f, hi);
        }
    }

    // ---- publish R (packed upper triangle): lane l holds row l ----
#pragma unroll
    for (int k = 0; k < NR; k++) {
        if (l <= k) {
            float lo, hi, rr, ri;
            UPK(are[0][k >> 1], lo, hi); rr = (k & 1) ? hi : lo;
            UPK(aim[0][k >> 1], lo, hi); ri = (k & 1) ? hi : lo;
            sRm[(k * (k + 1)) / 2 + l] = make_float2(rr, ri);
        }
    }
    __syncwarp();

    // ========== Q = X * R^{-1} back-substitution (packed row pairs) ==========
    u64 qAr[NR], qAi[NR], qBr[NR], qBi[NR];
#pragma unroll
    for (int k = 0; k < NR; k++) {
        const float2 y0 = sxm[SXI(l,      k)];
        const float2 y1 = sxm[SXI(l + 16, k)];
        const float2 y2 = sxm[SXI(l + 32, k)];
        const float2 y3 = sxm[SXI(l + 48, k)];
        u64 yAr = PK(y0.x, y1.x), yAi = PK(y0.y, y1.y);
        u64 yBr = PK(y2.x, y3.x), yBi = PK(y2.y, y3.y);
#pragma unroll
        for (int i = 0; i < k; i++) {
            const float2 rc = sRm[(k * (k + 1)) / 2 + i];   // R[i][k]
            const u64 nRr = DUP(-rc.x), Ri = DUP(rc.y), nRi = DUP(-rc.y);
            yAr = FMA2(nRr, qAr[i], FMA2(Ri,  qAi[i], yAr));
            yAi = FMA2(nRr, qAi[i], FMA2(nRi, qAr[i], yAi));
            yBr = FMA2(nRr, qBr[i], FMA2(Ri,  qBi[i], yBr));
            yBi = FMA2(nRr, qBi[i], FMA2(nRi, qBr[i], yBi));
        }
        const u64 IB = DUP(__fdividef(1.f, sRm[(k * (k + 1)) / 2 + k].x));
        qAr[k] = MUL2(yAr, IB); qAi[k] = MUL2(yAi, IB);
        qBr[k] = MUL2(yBr, IB); qBi[k] = MUL2(yBi, IB);
    }
    __syncwarp();   // everyone done reading X before overwrite

    // ---- stage Q back into sx (rotated) ----
#pragma unroll
    for (int k = 0; k < NR; k++) {
        float a0, b0_, a1, b1;
        UPK(qAr[k], a0, b0_); UPK(qAi[k], a1, b1);
        sxm[SXI(l,      k)] = make_float2(a0, a1);
        sxm[SXI(l + 16, k)] = make_float2(b0_, b1);
        UPK(qBr[k], a0, b0_); UPK(qBi[k], a1, b1);
        sxm[SXI(l + 32, k)] = make_float2(a0, a1);
        sxm[SXI(l + 48, k)] = make_float2(b0_, b1);
    }
    __syncwarp();

    // ---- coalesced store ----
    {
        float4* dst = (float4*)(out + (b0 + mw) * 2048);
#pragma unroll
        for (int i = 0; i < 32; i++) {
            const int idx = i * 32 + lane;
            const int m   = idx >> 9;
            const int rem = idx & 511;
            const int row = rem >> 3;
            const int cp  = rem & 7;
            const float2* base = sx + (mw + m) * 1024;
            const float2 v0 = base[SXI(row, 2 * cp)];
            const float2 v1 = base[SXI(row, 2 * cp + 1)];
            dst[idx] = make_float4(v0.x, v0.y, v1.x, v1.y);
        }
    }
}

extern "C" void kernel_launch(void* const* d_in, const int* in_sizes, int n_in,
                              void* d_out, int out_size)
{
    const float* x = (const float*)d_in[0];
    float* q = (float*)d_out;
    const int B = in_sizes[0] / (64 * NR * 2);   // 32768

    cudaFuncSetAttribute(qr_householder_kernel,
                         cudaFuncAttributeMaxDynamicSharedMemorySize,
                         SMEM_BYTES);

    const int grid = (B + MPB - 1) / MPB;
    qr_householder_kernel<<<grid, WPB * 32, SMEM_BYTES>>>(x, q, B);
}

// round 7
// speedup vs baseline: 1.0208x; 1.0208x over previous
#include <cuda_runtime.h>
#include <cuda_bf16.h>
#include <cstdint>

// Batched complex QR (Q only), LAPACK Householder convention.
//   Input : x [B, 64, 16, 2] float32   Output: q [B, 64, 16, 2] float32
//
// Two matrices per warp (16-lane groups, lane owns rows l, l+16, l+32, l+48).
// Single fused butterfly per elimination step; packed fma.rn.f32x2 everywhere.
// This round: 3 blocks/SM — rotated (pad-free) SMEM X staging + reg target 170.

typedef unsigned long long u64;
#define NR   16
#define WPB  4
#define MPB  (WPB * 2)
#define SX_F2 (MPB * 64 * 16)          // 8192 float2 = 64 KB
#define SR_F2 (MPB * 136)              // 1088 float2 = 8.5 KB
#define SMEM_BYTES ((SX_F2 + SR_F2) * (int)sizeof(float2))   // 74240
#define FULLM 0xffffffffu

__device__ __forceinline__ u64 PK(float lo, float hi) {
    u64 r; asm("mov.b64 %0,{%1,%2};" : "=l"(r) : "f"(lo), "f"(hi)); return r;
}
__device__ __forceinline__ void UPK(u64 v, float& lo, float& hi) {
    asm("mov.b64 {%0,%1},%2;" : "=f"(lo), "=f"(hi) : "l"(v));
}
__device__ __forceinline__ u64 DUP(float x) { return PK(x, x); }
__device__ __forceinline__ u64 FMA2(u64 a, u64 b, u64 c) {
    u64 d; asm("fma.rn.f32x2 %0,%1,%2,%3;" : "=l"(d) : "l"(a), "l"(b), "l"(c)); return d;
}
__device__ __forceinline__ u64 MUL2(u64 a, u64 b) {
    u64 d; asm("mul.rn.f32x2 %0,%1,%2;" : "=l"(d) : "l"(a), "l"(b)); return d;
}
__device__ __forceinline__ u64 ADD2(u64 a, u64 b) {
    u64 d; asm("add.rn.f32x2 %0,%1,%2;" : "=l"(d) : "l"(a), "l"(b)); return d;
}
__device__ __forceinline__ u64 SHX2(u64 v, int s) {
    float a, b; UPK(v, a, b);
    a = __shfl_xor_sync(FULLM, a, s);
    b = __shfl_xor_sync(FULLM, b, s);
    return PK(a, b);
}
__device__ __forceinline__ u64 SHI2(u64 v, int src) {
    float a, b; UPK(v, a, b);
    a = __shfl_sync(FULLM, a, src);
    b = __shfl_sync(FULLM, b, src);
    return PK(a, b);
}
// rotated (pad-free, conflict-free) sx addressing, in float2 units
__device__ __forceinline__ int SXI(int row, int col) {
    return row * 16 + ((col + row) & 15);
}

__global__ void __launch_bounds__(128, 3)
qr_householder_kernel(const float* __restrict__ in,
                      float* __restrict__ out,
                      int B)
{
    extern __shared__ float2 smem[];
    float2* sx = smem;             // [MPB][64][16], rotated rows
    float2* sR = smem + SX_F2;     // packed upper triangles, 136 per matrix

    const int tid  = threadIdx.x;
    const int warp = tid >> 5;
    const int lane = tid & 31;
    const int g    = lane >> 4;
    const int l    = lane & 15;
    const int mw   = warp * 2;
    const long long b0 = (long long)blockIdx.x * MPB;
    if (b0 + mw >= B) return;

    // ---- coalesced load of this warp's 2 matrices -> rotated SMEM ----
    {
        const float4* src = (const float4*)(in + (b0 + mw) * 2048);
#pragma unroll
        for (int i = 0; i < 32; i++) {
            const int idx = i * 32 + lane;
            const float4 v = src[idx];
            const int m   = idx >> 9;
            const int rem = idx & 511;
            const int row = rem >> 3;
            const int cp  = rem & 7;
            float2* base = sx + (mw + m) * 1024;
            base[SXI(row, 2 * cp)]     = make_float2(v.x, v.y);
            base[SXI(row, 2 * cp + 1)] = make_float2(v.z, v.w);
        }
    }
    __syncwarp();

    float2* sxm = sx + (mw + g) * 1024;
    float2* sRm = sR + (mw + g) * 136;

    // ---- working copy, packed planes: column pair p = cols (2p, 2p+1) ----
    u64 are[4][8], aim[4][8];
#pragma unroll
    for (int r = 0; r < 4; r++)
#pragma unroll
        for (int p = 0; p < 8; p++) {
            const float2 c0 = sxm[SXI(l + 16 * r, 2 * p)];
            const float2 c1 = sxm[SXI(l + 16 * r, 2 * p + 1)];
            are[r][p] = PK(c0.x, c1.x);
            aim[r][p] = PK(c0.y, c1.y);
        }

    // ================= Householder elimination (cgeqrf) =================
#pragma unroll
    for (int j = 0; j < NR; j++) {
        const int jp   = j >> 1;
        const int srcj = (g << 4) | j;

        float xr[4], xi[4];
#pragma unroll
        for (int r = 0; r < 4; r++) {
            float lo, hi; UPK(are[r][jp], lo, hi);
            xr[r] = (j & 1) ? hi : lo;
            UPK(aim[r][jp], lo, hi);
            xi[r] = (j & 1) ? hi : lo;
        }
        const float alr = __shfl_sync(FULLM, xr[0], srcj);   // alpha
        const float ali = __shfl_sync(FULLM, xi[0], srcj);
        const float x0r = (l > j) ? xr[0] : 0.f;
        const float x0i = (l > j) ? xi[0] : 0.f;

        float t = xr[1]*xr[1] + xi[1]*xi[1] + xr[2]*xr[2] + xi[2]*xi[2]
                + xr[3]*xr[3] + xi[3]*xi[3] + x0r*x0r + x0i*x0i;

        // u_k = sum_tail conj(x) * a_k   (packed partials)
        u64 ur[8], ui[8];
        {
            const u64 X1 = DUP(xr[1]), Y1 = DUP(xi[1]), nY1 = DUP(-xi[1]);
            const u64 X2 = DUP(xr[2]), Y2 = DUP(xi[2]), nY2 = DUP(-xi[2]);
            const u64 X3 = DUP(xr[3]), Y3 = DUP(xi[3]), nY3 = DUP(-xi[3]);
            const u64 X0 = DUP(x0r),   Y0 = DUP(x0i),   nY0 = DUP(-x0i);
#pragma unroll
            for (int p = 0; p < 8; p++) {
                if (2 * p + 1 <= j) continue;
                u64 r_ = FMA2(X1, are[1][p], MUL2(Y1,  aim[1][p]));
                u64 i_ = FMA2(X1, aim[1][p], MUL2(nY1, are[1][p]));
                r_ = FMA2(X2, are[2][p], FMA2(Y2,  aim[2][p], r_));
                i_ = FMA2(X2, aim[2][p], FMA2(nY2, are[2][p], i_));
                r_ = FMA2(X3, are[3][p], FMA2(Y3,  aim[3][p], r_));
                i_ = FMA2(X3, aim[3][p], FMA2(nY3, are[3][p], i_));
                r_ = FMA2(X0, are[0][p], FMA2(Y0,  aim[0][p], r_));
                i_ = FMA2(X0, aim[0][p], FMA2(nY0, are[0][p], i_));
                ur[p] = r_; ui[p] = i_;
            }
        }

        // single fused butterfly: t + all u_k
#pragma unroll
        for (int s = 8; s; s >>= 1) {
            t += __shfl_xor_sync(FULLM, t, s);
#pragma unroll
            for (int p = 0; p < 8; p++) {
                if (2 * p + 1 <= j) continue;
                ur[p] = ADD2(ur[p], SHX2(ur[p], s));
                ui[p] = ADD2(ui[p], SHX2(ui[p], s));
            }
        }

        // Householder scalars (LAPACK clarfg convention), rsqrt-based
        float bet, idr, idi, ctr, cti;
        if (t == 0.f && ali == 0.f) {
            bet = alr; idr = 0.f; idi = 0.f; ctr = 0.f; cti = 0.f;  // tau = 0
        } else {
            const float ss = alr * alr + ali * ali + t;
            const float rn = rsqrtf(ss);
            const float nrm = ss * rn;
            const float sgn = (alr >= 0.f) ? 1.f : -1.f;
            bet = -sgn * nrm;
            const float ib = -sgn * rn;               // 1/bet
            const float dr = alr - bet, di = ali;
            const float dd = __fdividef(1.f, dr * dr + di * di);
            idr = dr * dd; idi = -di * dd;            // 1/(alpha-beta)
            ctr = (bet - alr) * ib; cti = ali * ib;   // conj(tau)
        }

        // reflector v over this lane's rows
        float vr0, vi0;
        if (l > j)       { vr0 = idr*xr[0] - idi*xi[0]; vi0 = idr*xi[0] + idi*xr[0]; }
        else if (l == j) { vr0 = 1.f; vi0 = 0.f; }
        else             { vr0 = 0.f; vi0 = 0.f; }
        const float vr1 = idr*xr[1] - idi*xi[1], vi1 = idr*xi[1] + idi*xr[1];
        const float vr2 = idr*xr[2] - idi*xi[2], vi2 = idr*xi[2] + idi*xr[2];
        const float vr3 = idr*xr[3] - idi*xi[3], vi3 = idr*xi[3] + idi*xr[3];
        const u64 V0r = DUP(vr0), V0i = DUP(vi0), V1r = DUP(vr1), V1i = DUP(vi1);
        const u64 V2r = DUP(vr2), V2i = DUP(vi2), V3r = DUP(vr3), V3i = DUP(vi3);
        const u64 IDR = DUP(idr), IDI = DUP(idi), nIDI = DUP(-idi);
        const u64 CTR = DUP(ctr), nCTR = DUP(-ctr), CTI = DUP(cti), nCTI = DUP(-cti);

        // per pair: row-j broadcast, w = ajk + conj(inv)*u, g = ctau*w, a -= g*v
        // (loop order starts at the next step's critical pair naturally)
#pragma unroll
        for (int p = 0; p < 8; p++) {
            if (2 * p + 1 <= j) continue;
            const u64 ajr = SHI2(are[0][p], srcj);
            const u64 aji = SHI2(aim[0][p], srcj);
            const u64 wr = FMA2(IDR, ur[p], FMA2(IDI,  ui[p], ajr));
            const u64 wi = FMA2(IDR, ui[p], FMA2(nIDI, ur[p], aji));
            const u64 ngr = FMA2(nCTR, wr, MUL2(CTI,  wi));   // -Re(g)
            const u64 gi  = FMA2(CTR,  wi, MUL2(CTI,  wr));   //  Im(g)
            const u64 ngi = FMA2(nCTR, wi, MUL2(nCTI, wr));   // -Im(g)
            are[0][p] = FMA2(ngr, V0r, FMA2(gi,  V0i, are[0][p]));
            aim[0][p] = FMA2(ngr, V0i, FMA2(ngi, V0r, aim[0][p]));
            are[1][p] = FMA2(ngr, V1r, FMA2(gi,  V1i, are[1][p]));
            aim[1][p] = FMA2(ngr, V1i, FMA2(ngi, V1r, aim[1][p]));
            are[2][p] = FMA2(ngr, V2r, FMA2(gi,  V2i, are[2][p]));
            aim[2][p] = FMA2(ngr, V2i, FMA2(ngi, V2r, aim[2][p]));
            are[3][p] = FMA2(ngr, V3r, FMA2(gi,  V3i, are[3][p]));
            aim[3][p] = FMA2(ngr, V3i, FMA2(ngi, V3r, aim[3][p]));
        }

        // R diagonal (beta, real) on lane j
        if (l == j) {
            float lo, hi;
            UPK(are[0][jp], lo, hi);
            are[0][jp] = (j & 1) ? PK(lo, bet) : PK(bet, hi);
            UPK(aim[0][jp], lo, hi);
            aim[0][jp] = (j & 1) ? PK(lo, 0.f) : PK(0.f, hi);
        }
    }

    // ---- publish R (packed upper triangle): lane l holds row l ----
#pragma unroll
    for (int k = 0; k < NR; k++) {
        if (l <= k) {
            float lo, hi, rr, ri;
            UPK(are[0][k >> 1], lo, hi); rr = (k & 1) ? hi : lo;
            UPK(aim[0][k >> 1], lo, hi); ri = (k & 1) ? hi : lo;
            sRm[(k * (k + 1)) / 2 + l] = make_float2(rr, ri);
        }
    }
    __syncwarp();

    // ========== Q = X * R^{-1} back-substitution (packed row pairs) ==========
    u64 qAr[NR], qAi[NR], qBr[NR], qBi[NR];
#pragma unroll
    for (int k = 0; k < NR; k++) {
        const float2 y0 = sxm[SXI(l,      k)];
        const float2 y1 = sxm[SXI(l + 16, k)];
        const float2 y2 = sxm[SXI(l + 32, k)];
        const float2 y3 = sxm[SXI(l + 48, k)];
        u64 yAr = PK(y0.x, y1.x), yAi = PK(y0.y, y1.y);
        u64 yBr = PK(y2.x, y3.x), yBi = PK(y2.y, y3.y);
#pragma unroll
        for (int i = 0; i < k; i++) {
            const float2 rc = sRm[(k * (k + 1)) / 2 + i];   // R[i][k]
            const u64 nRr = DUP(-rc.x), Ri = DUP(rc.y), nRi = DUP(-rc.y);
            yAr = FMA2(nRr, qAr[i], FMA2(Ri,  qAi[i], yAr));
            yAi = FMA2(nRr, qAi[i], FMA2(nRi, qAr[i], yAi));
            yBr = FMA2(nRr, qBr[i], FMA2(Ri,  qBi[i], yBr));
            yBi = FMA2(nRr, qBi[i], FMA2(nRi, qBr[i], yBi));
        }
        const u64 IB = DUP(__fdividef(1.f, sRm[(k * (k + 1)) / 2 + k].x));
        qAr[k] = MUL2(yAr, IB); qAi[k] = MUL2(yAi, IB);
        qBr[k] = MUL2(yBr, IB); qBi[k] = MUL2(yBi, IB);
    }
    __syncwarp();   // everyone done reading X before overwrite

    // ---- stage Q back into sx (rotated) ----
#pragma unroll
    for (int k = 0; k < NR; k++) {
        float a0, b0_, a1, b1;
        UPK(qAr[k], a0, b0_); UPK(qAi[k], a1, b1);
        sxm[SXI(l,      k)] = make_float2(a0, a1);
        sxm[SXI(l + 16, k)] = make_float2(b0_, b1);
        UPK(qBr[k], a0, b0_); UPK(qBi[k], a1, b1);
        sxm[SXI(l + 32, k)] = make_float2(a0, a1);
        sxm[SXI(l + 48, k)] = make_float2(b0_, b1);
    }
    __syncwarp();

    // ---- coalesced store ----
    {
        float4* dst = (float4*)(out + (b0 + mw) * 2048);
#pragma unroll
        for (int i = 0; i < 32; i++) {
            const int idx = i * 32 + lane;
            const int m   = idx >> 9;
            const int rem = idx & 511;
            const int row = rem >> 3;
            const int cp  = rem & 7;
            const float2* base = sx + (mw + m) * 1024;
            const float2 v0 = base[SXI(row, 2 * cp)];
            const float2 v1 = base[SXI(row, 2 * cp + 1)];
            dst[idx] = make_float4(v0.x, v0.y, v1.x, v1.y);
        }
    }
}

extern "C" void kernel_launch(void* const* d_in, const int* in_sizes, int n_in,
                              void* d_out, int out_size)
{
    const float* x = (const float*)d_in[0];
    float* q = (float*)d_out;
    const int B = in_sizes[0] / (64 * NR * 2);   // 32768

    cudaFuncSetAttribute(qr_householder_kernel,
                         cudaFuncAttributeMaxDynamicSharedMemorySize,
                         SMEM_BYTES);

    const int grid = (B + MPB - 1) / MPB;
    qr_householder_kernel<<<grid, WPB * 32, SMEM_BYTES>>>(x, q, B);
}

// round 8
// speedup vs baseline: 1.1205x; 1.0976x over previous
#include <cuda_runtime.h>
#include <cuda_bf16.h>
#include <cstdint>

// Batched complex QR (Q only), LAPACK Householder convention.
//   Input : x [B, 64, 16, 2] float32   Output: q [B, 64, 16, 2] float32
//
// ONE matrix per 32-lane warp. lane = (cg = lane>>3, rl = lane&7):
//   owns rows {rl+8t, t=0..7} x interleaved cols {cg+4u, u=0..3}.
// Working copy A[8][4] packed (re,im) u64 -> 64 regs -> 4 blocks/SM.
// Butterflies: 3 rounds over the 8 row-lanes. Dot products via P/Q
// two-accumulator trick (2 FMA2/elem). Phase 2 row-distributed, shuffle-free.

typedef unsigned long long u64;
#define NR    16
#define WPB   4                        // warps (= matrices) per block
#define ROWF2 17                       // padded row stride in float2
#define SXPM  (64 * ROWF2)             // 1088 float2 per matrix
#define SRPM  136                      // packed R upper triangle
#define SMEM_BYTES (WPB * (SXPM + SRPM) * (int)sizeof(float2))   // 39168
#define FULLM 0xffffffffu

__device__ __forceinline__ u64 PK(float lo, float hi) {
    u64 r; asm("mov.b64 %0,{%1,%2};" : "=l"(r) : "f"(lo), "f"(hi)); return r;
}
__device__ __forceinline__ void UPK(u64 v, float& lo, float& hi) {
    asm("mov.b64 {%0,%1},%2;" : "=f"(lo), "=f"(hi) : "l"(v));
}
__device__ __forceinline__ u64 DUP(float x) { return PK(x, x); }
__device__ __forceinline__ u64 SWN(u64 z) {  // (im, -re)
    float a, b; UPK(z, a, b); return PK(b, -a);
}
__device__ __forceinline__ u64 NSW(u64 z) {  // (-im, re)
    float a, b; UPK(z, a, b); return PK(-b, a);
}
__device__ __forceinline__ u64 FMA2(u64 a, u64 b, u64 c) {
    u64 d; asm("fma.rn.f32x2 %0,%1,%2,%3;" : "=l"(d) : "l"(a), "l"(b), "l"(c)); return d;
}
__device__ __forceinline__ u64 MUL2(u64 a, u64 b) {
    u64 d; asm("mul.rn.f32x2 %0,%1,%2;" : "=l"(d) : "l"(a), "l"(b)); return d;
}
__device__ __forceinline__ u64 ADD2(u64 a, u64 b) {
    u64 d; asm("add.rn.f32x2 %0,%1,%2;" : "=l"(d) : "l"(a), "l"(b)); return d;
}
__device__ __forceinline__ u64 SHX2(u64 v, int s) {
    float a, b; UPK(v, a, b);
    a = __shfl_xor_sync(FULLM, a, s);
    b = __shfl_xor_sync(FULLM, b, s);
    return PK(a, b);
}
__device__ __forceinline__ u64 SHI2(u64 v, int src) {
    float a, b; UPK(v, a, b);
    a = __shfl_sync(FULLM, a, src);
    b = __shfl_sync(FULLM, b, src);
    return PK(a, b);
}

__global__ void __launch_bounds__(128, 4)
qr_householder_kernel(const float* __restrict__ in,
                      float* __restrict__ out,
                      int B)
{
    extern __shared__ float2 smem[];
    const int tid  = threadIdx.x;
    const int warp = tid >> 5;
    const int lane = tid & 31;
    const int cg   = lane >> 3;     // column group: owns cols cg+4u
    const int rl   = lane & 7;      // row lane:     owns rows rl+8t
    const long long b = (long long)blockIdx.x * WPB + warp;
    if (b >= B) return;

    float2* sxm = smem + warp * (SXPM + SRPM);
    float2* sRm = sxm + SXPM;

    // ---- coalesced load -> padded SMEM ----
    {
        const float4* src = (const float4*)(in + b * 2048);
#pragma unroll
        for (int it = 0; it < 16; it++) {
            const int idx = it * 32 + lane;         // 512 float4 units
            const float4 v = src[idx];
            const int row = idx >> 3, cp = idx & 7;
            sxm[row * ROWF2 + 2 * cp]     = make_float2(v.x, v.y);
            sxm[row * ROWF2 + 2 * cp + 1] = make_float2(v.z, v.w);
        }
    }
    __syncwarp();

    // ---- register fill: A[t][u] = (row rl+8t, col cg+4u), packed (re,im) ----
    u64 A[8][4];
#pragma unroll
    for (int t = 0; t < 8; t++)
#pragma unroll
        for (int u = 0; u < 4; u++) {
            const float2 c = sxm[(rl + 8 * t) * ROWF2 + (cg + 4 * u)];
            A[t][u] = PK(c.x, c.y);
        }

    // ================= Householder elimination (cgeqrf) =================
#pragma unroll
    for (int j = 0; j < NR; j++) {
        const int uj = j >> 2, cgj = j & 3, tj = j >> 3, rlj = j & 7;

        // broadcast column j across groups (lane gets x at ITS rows)
        u64 xb[8];
#pragma unroll
        for (int t = tj; t < 8; t++)
            xb[t] = SHI2(A[t][uj], (cgj << 3) | rl);

        // alpha = x[row j] (lane rlj in group 0 has it in xb[tj])
        float alr, ali;
        { u64 al = SHI2(xb[tj], rlj); UPK(al, alr, ali); }

        // mask: keep only rows > j in the tj slot
        if (!(rl > rlj)) xb[tj] = 0ull;

        // P/Q dot partials + tail-norm over this lane's rows
        float nt = 0.f;
        u64 P[4], Q[4];
#pragma unroll
        for (int u = 0; u < 4; u++)
            if (4 * u + 3 > j) { P[u] = 0ull; Q[u] = 0ull; }
#pragma unroll
        for (int t = tj; t < 8; t++) {
            float xr, xi; UPK(xb[t], xr, xi);
            nt = fmaf(xr, xr, fmaf(xi, xi, nt));
            const u64 XR = DUP(xr), XI = DUP(xi);
#pragma unroll
            for (int u = 0; u < 4; u++)
                if (4 * u + 3 > j) {
                    P[u] = FMA2(XR, A[t][u], P[u]);
                    Q[u] = FMA2(XI, A[t][u], Q[u]);
                }
        }
        // combine: u = sum conj(x)*a = (P.lo + Q.hi, P.hi - Q.lo)
        u64 uu[4];
#pragma unroll
        for (int u = 0; u < 4; u++)
            if (4 * u + 3 > j) {
                float pr, pi, qr2, qi2;
                UPK(P[u], pr, pi); UPK(Q[u], qr2, qi2);
                uu[u] = PK(pr + qi2, pi - qr2);
            }
        // 3-round butterfly within the 8-lane row group
#pragma unroll
        for (int s = 4; s; s >>= 1) {
            nt += __shfl_xor_sync(FULLM, nt, s);
#pragma unroll
            for (int u = 0; u < 4; u++)
                if (4 * u + 3 > j)
                    uu[u] = ADD2(uu[u], SHX2(uu[u], s));
        }

        // Householder scalars (LAPACK clarfg convention)
        float bet, idr, idi, ctr, cti;
        if (nt == 0.f && ali == 0.f) {
            bet = alr; idr = 0.f; idi = 0.f; ctr = 0.f; cti = 0.f;  // tau = 0
        } else {
            const float ss  = fmaf(alr, alr, fmaf(ali, ali, nt));
            const float rn  = rsqrtf(ss);
            const float nrm = ss * rn;
            const float sgn = (alr >= 0.f) ? 1.f : -1.f;
            bet = -sgn * nrm;
            const float ib = -sgn * rn;                  // 1/bet
            const float dr = alr - bet, di = ali;
            const float dd = __fdividef(1.f, fmaf(dr, dr, di * di));
            idr = dr * dd; idi = -di * dd;               // 1/(alpha-beta)
            ctr = (bet - alr) * ib; cti = ali * ib;      // conj(tau)
        }
        const u64 IDR = DUP(idr), IDI = DUP(idi);
        const u64 CTR = DUP(ctr), CTI = DUP(cti);

        // per active column: row-j broadcast, w = ajk + conj(inv)*u, g = ctau*w
        u64 nGr[4], Gi[4];
#pragma unroll
        for (int u = 0; u < 4; u++)
            if (4 * u + 3 > j) {
                const u64 ajk = SHI2(A[tj][u], (cg << 3) | rlj);
                const u64 w = FMA2(IDR, uu[u], FMA2(IDI, SWN(uu[u]), ajk));
                const u64 g = FMA2(CTR, w, MUL2(CTI, NSW(w)));
                float gr, gi2; UPK(g, gr, gi2);
                nGr[u] = DUP(-gr); Gi[u] = DUP(gi2);
            }

        // rank-1 update: A -= g * v   (v = x*inv below diag, 1 at row j)
#pragma unroll
        for (int t = tj; t < 8; t++) {
            u64 vt = FMA2(IDR, xb[t], MUL2(IDI, NSW(xb[t])));
            if (t == tj && rl == rlj) vt = PK(1.f, 0.f);
            const u64 svt = SWN(vt);
#pragma unroll
            for (int u = 0; u < 4; u++)
                if (4 * u + 3 > j) {
                    if (cg + 4 * u > j)   // runtime: only true trailing cols
                        A[t][u] = FMA2(nGr[u], vt, FMA2(Gi[u], svt, A[t][u]));
                }
        }
        // R diagonal (beta, real)
        if (cg == cgj && rl == rlj) A[tj][uj] = PK(bet, 0.f);
    }

    // ---- publish R (packed upper triangle) ----
#pragma unroll
    for (int u = 0; u < 4; u++) {
        const int col = cg + 4 * u;
#pragma unroll
        for (int t = 0; t < 2; t++) {      // rows 0..15 live in t=0,1
            const int i = rl + 8 * t;
            if (i <= col) {
                float rr, ri; UPK(A[t][u], rr, ri);
                sRm[(col * (col + 1)) / 2 + i] = make_float2(rr, ri);
            }
        }
    }
    __syncwarp();

    // ========== Q = X * R^{-1} back-substitution (rows l, l+32) ==========
    u64 qr[NR], qi[NR];
#pragma unroll
    for (int k = 0; k < NR; k++) {
        const float2 y0 = sxm[lane * ROWF2 + k];
        const float2 y1 = sxm[(lane + 32) * ROWF2 + k];
        u64 yr = PK(y0.x, y1.x), yi = PK(y0.y, y1.y);
#pragma unroll
        for (int i = 0; i < k; i++) {
            const float2 rc = sRm[(k * (k + 1)) / 2 + i];   // R[i][k]
            const u64 nRr = DUP(-rc.x), RiD = DUP(rc.y), nRi = DUP(-rc.y);
            yr = FMA2(nRr, qr[i], FMA2(RiD, qi[i], yr));
            yi = FMA2(nRr, qi[i], FMA2(nRi, qr[i], yi));
        }
        const u64 IB = DUP(__fdividef(1.f, sRm[(k * (k + 1)) / 2 + k].x));
        qr[k] = MUL2(yr, IB); qi[k] = MUL2(yi, IB);
    }

    // ---- stage Q back into sx (this lane's own rows only) ----
#pragma unroll
    for (int k = 0; k < NR; k++) {
        float r0, r1, i0, i1;
        UPK(qr[k], r0, r1); UPK(qi[k], i0, i1);
        sxm[lane * ROWF2 + k]        = make_float2(r0, i0);
        sxm[(lane + 32) * ROWF2 + k] = make_float2(r1, i1);
    }
    __syncwarp();

    // ---- coalesced store ----
    {
        float4* dst = (float4*)(out + b * 2048);
#pragma unroll
        for (int it = 0; it < 16; it++) {
            const int idx = it * 32 + lane;
            const int row = idx >> 3, cp = idx & 7;
            const float2 v0 = sxm[row * ROWF2 + 2 * cp];
            const float2 v1 = sxm[row * ROWF2 + 2 * cp + 1];
            dst[idx] = make_float4(v0.x, v0.y, v1.x, v1.y);
        }
    }
}

extern "C" void kernel_launch(void* const* d_in, const int* in_sizes, int n_in,
                              void* d_out, int out_size)
{
    const float* x = (const float*)d_in[0];
    float* q = (float*)d_out;
    const int B = in_sizes[0] / (64 * NR * 2);   // 32768

    cudaFuncSetAttribute(qr_householder_kernel,
                         cudaFuncAttributeMaxDynamicSharedMemorySize,
                         SMEM_BYTES);

    const int grid = (B + WPB - 1) / WPB;
    qr_householder_kernel<<<grid, WPB * 32, SMEM_BYTES>>>(x, q, B);
}